// round 14
// baseline (speedup 1.0000x reference)
#include <cuda_runtime.h>
#include <cstdint>

// Problem constants (fixed by dataset: B=16, H=1024, W=2048, G=8, C=19)
#define NB      524288
#define NC      19
#define WID     2048
#define HEI     1024
#define GS      8
#define BLOCKS_PER_TILE 128                    // half a block-row
#define NTILES  (NB/BLOCKS_PER_TILE)           // 4096
#define TGT_ROW_BYTES 4096                     // 1024 px * 4B per strip row
#define TGT_BYTES (8*TGT_ROW_BYTES)            // 32768
#define PRED_BYTES (BLOCKS_PER_TILE*NC*4)      // 9728 (16B multiple)
#define STAGE_BYTES (TGT_BYTES + PRED_BYTES)   // 42496
#define NSTAGE  5
#define NTHREADS 512
#define GRID    152                            // 1 CTA per SM
#define V_PER_TILE (BLOCKS_PER_TILE*NC/4)      // 608 float4

// Allocation-free scratch (__device__ globals per harness rules)
__device__ double       g_partials[GRID];
__device__ unsigned int g_count = 0;           // self-resetting completion counter

// Numerically stable softplus: max(x,0) + log(1 + exp(-|x|))
__device__ __forceinline__ float softplus_f(float x)
{
    float e = __expf(-fabsf(x));
    return fmaxf(x, 0.0f) + __logf(1.0f + e);
}

__device__ __forceinline__ void mbar_init(uint32_t mbar, unsigned count)
{
    asm volatile("mbarrier.init.shared.b64 [%0], %1;" :: "r"(mbar), "r"(count) : "memory");
}

__device__ __forceinline__ void mbar_wait(uint32_t mbar, unsigned phase)
{
    asm volatile(
        "{\n\t.reg .pred P;\n\t"
        "WAIT_%=:\n\t"
        "mbarrier.try_wait.parity.acquire.cta.shared::cta.b64 P, [%0], %1, 0x989680;\n\t"
        "@P bra DONE_%=;\n\t"
        "bra WAIT_%=;\n\t"
        "DONE_%=:\n\t}"
        :: "r"(mbar), "r"(phase) : "memory");
}

__device__ __forceinline__ void bulk_cp(uint32_t dst_smem, const void* src,
                                        unsigned bytes, uint32_t mbar)
{
    asm volatile(
        "cp.async.bulk.shared::cluster.global.mbarrier::complete_tx::bytes "
        "[%0], [%1], %2, [%3];"
        :: "r"(dst_smem), "l"(src), "r"(bytes), "r"(mbar) : "memory");
}

__device__ __forceinline__ const char* tile_tgt_src(const int* tgt, unsigned tile)
{
    unsigned half = tile & 1u;
    unsigned bh   = (tile >> 1) & 127u;
    unsigned bimg = tile >> 8;
    return (const char*)(tgt
        + ((size_t)(bimg * HEI + bh * GS)) * WID + (size_t)half * 1024u);
}

// Full tile issue (prologue): expect_tx + 8 target rows + preds.
__device__ __forceinline__ void issue_tile(const int* tgt, const float* preds,
                                           unsigned tile, uint32_t stage, uint32_t mbar)
{
    asm volatile("mbarrier.arrive.expect_tx.shared.b64 _, [%0], %1;"
                 :: "r"(mbar), "r"((unsigned)STAGE_BYTES) : "memory");
    const char* tsrc = tile_tgt_src(tgt, tile);
#pragma unroll
    for (int r = 0; r < 8; r++)
        bulk_cp(stage + r * TGT_ROW_BYTES, tsrc + (size_t)r * WID * 4,
                TGT_ROW_BYTES, mbar);
    bulk_cp(stage + TGT_BYTES, (const char*)preds + (size_t)tile * PRED_BYTES,
            PRED_BYTES, mbar);
}

// ---------------------------------------------------------------------------
// 5-stage TMA pipeline, 512 threads, 1 CTA/SM (212.5 KB smem).
// ~4 tiles (~170KB) in flight per CTA while the 5th is consumed.
// Split refill: targets re-issue after the mask barrier (region dead),
// preds after the consume barrier -> requests flow during compute.
// ---------------------------------------------------------------------------
__global__ void __launch_bounds__(NTHREADS)
fused_kernel(const int*   __restrict__ tgt,
             const float* __restrict__ preds,
             float*       __restrict__ out)
{
    extern __shared__ char stage_mem[];                 // NSTAGE * STAGE_BYTES
    __shared__ unsigned long long mbar_store[NSTAGE];
    __shared__ unsigned int sm_mask[BLOCKS_PER_TILE + 1];
    __shared__ float  ws[16];
    __shared__ double sh[256];

    const unsigned tid  = threadIdx.x;
    const unsigned lane = tid & 31u;
    const unsigned wix  = tid >> 5;                     // 0..15
    const unsigned cta  = blockIdx.x;

    const uint32_t stage0 = (uint32_t)__cvta_generic_to_shared(stage_mem);
    const uint32_t mbb    = (uint32_t)__cvta_generic_to_shared(&mbar_store[0]);

    if (tid == 0) {
#pragma unroll
        for (int k = 0; k < NSTAGE; k++) mbar_init(mbb + 8u * k, 1);
        asm volatile("fence.proxy.async.shared::cta;" ::: "memory");
        // Prologue: fill all 5 stages (every CTA has >= 26 tiles)
#pragma unroll
        for (unsigned k = 0; k < NSTAGE; k++)
            issue_tile(tgt, preds, cta + k * GRID,
                       stage0 + k * STAGE_BYTES, mbb + 8u * k);
    }
    __syncthreads();

    float s = 0.0f;
    unsigned k = 0, ph = 0;

    for (unsigned tile = cta; tile < NTILES; tile += GRID) {
        const uint32_t  stg  = stage0 + k * STAGE_BYTES;
        const char*     stgp = stage_mem + (size_t)k * STAGE_BYTES;
        const uint32_t  mb   = mbb + 8u * k;
        const unsigned  nt   = tile + NSTAGE * GRID;    // refill tile (if any)

        mbar_wait(mb, ph);

        // ---- masks: 4 threads per block (half h, row-group rg) ----
        {
            unsigned blk = tid >> 2;
            unsigned h   = tid & 1u;            // 16B half of the 32B block row
            unsigned rg  = (tid >> 1) & 1u;     // rows rg*4 .. rg*4+3
            unsigned m = 0u;
#pragma unroll
            for (int r = 0; r < 4; r++) {
                int4 v = *(const int4*)(stgp + (rg * 4u + r) * TGT_ROW_BYTES
                                        + blk * 32u + h * 16u);
                m |= (1u << v.x) | (1u << v.y) | (1u << v.z) | (1u << v.w);
            }
            m |= __shfl_xor_sync(0xffffffffu, m, 1);   // merge halves
            m |= __shfl_xor_sync(0xffffffffu, m, 2);   // merge row groups
            if ((tid & 3u) == 0u) sm_mask[blk] = m;
            if (tid == 0u) sm_mask[BLOCKS_PER_TILE] = 0u;
        }
        __syncthreads();          // masks visible; targets region dead

        // refill targets early: overlaps the preds compute below
        if (tid == 0u && nt < NTILES) {
            asm volatile("mbarrier.arrive.expect_tx.shared.b64 _, [%0], %1;"
                         :: "r"(mb), "r"((unsigned)STAGE_BYTES) : "memory");
            const char* tsrc = tile_tgt_src(tgt, nt);
#pragma unroll
            for (int r = 0; r < 8; r++)
                bulk_cp(stg + r * TGT_ROW_BYTES, tsrc + (size_t)r * WID * 4,
                        TGT_ROW_BYTES, mb);
        }

        // ---- preds: 608 float4 from smem, softplus + correction ----
        const float4* pvs = (const float4*)(stgp + TGT_BYTES);
#pragma unroll
        for (int it = 0; it < 2; it++) {
            unsigned j = tid + (unsigned)it * NTHREADS;
            if (it == 1 && tid >= (V_PER_TILE - NTHREADS)) break;  // tail: tid<96
            unsigned e0 = j * 4u;
            unsigned q  = e0 / 19u;                 // 0..127 (magic div)
            unsigned c0 = e0 - q * 19u;             // 0..18
            unsigned mm = (sm_mask[q] | (sm_mask[q + 1] << 19)) >> c0;
            float4 x = pvs[j];
            s += softplus_f(x.x) + softplus_f(x.y)
               + softplus_f(x.z) + softplus_f(x.w);
            if (mm & 1u) s -= x.x;
            if (mm & 2u) s -= x.y;
            if (mm & 4u) s -= x.z;
            if (mm & 8u) s -= x.w;
        }
        __syncthreads();          // all preds reads of this stage done

        // refill preds (completes the stage's expect_tx)
        if (tid == 0u && nt < NTILES)
            bulk_cp(stg + TGT_BYTES,
                    (const char*)preds + (size_t)nt * PRED_BYTES,
                    PRED_BYTES, mb);

        if (++k == NSTAGE) { k = 0; ph ^= 1u; }
    }

    // ---- per-CTA fixed-tree reduction -> double partial ----
#pragma unroll
    for (int o = 16; o > 0; o >>= 1)
        s += __shfl_xor_sync(0xffffffffu, s, o);
    if (lane == 0u) ws[wix] = s;
    __syncthreads();
    if (tid < 32u) {
        float v = (tid < 16u) ? ws[tid] : 0.0f;
#pragma unroll
        for (int o = 8; o > 0; o >>= 1)
            v += __shfl_xor_sync(0xffffffffu, v, o);
        if (tid == 0u) {
            g_partials[cta] = (double)v;
            __threadfence();
            unsigned done = atomicAdd(&g_count, 1u);
            ws[0] = (done == (unsigned)(GRID - 1)) ? 1.0f : 0.0f;
        }
    }
    __syncthreads();
    if (ws[0] == 0.0f) return;

    // ---- Last CTA: deterministic final reduction over CTA partials ----
    double d = (tid < (unsigned)GRID) ? g_partials[tid] : 0.0;
    if (tid < 256u) sh[tid] = 0.0;
    __syncthreads();
    if (tid < (unsigned)GRID) sh[tid & 127u] = 0.0;   // no-op keep layout simple
    __syncthreads();
    // simple deterministic tree over 512 slots via shared (GRID=152 <= 512)
    {
        __shared__ double sh2[NTHREADS];
        sh2[tid] = d;
        __syncthreads();
#pragma unroll
        for (int o = NTHREADS / 2; o > 0; o >>= 1) {
            if (tid < (unsigned)o) sh2[tid] += sh2[tid + o];
            __syncthreads();
        }
        if (tid == 0) {
            out[0] = (float)(sh2[0] / ((double)NB * (double)NC));
            g_count = 0;                 // reset for next graph replay
        }
    }
}

// ---------------------------------------------------------------------------
extern "C" void kernel_launch(void* const* d_in, const int* in_sizes, int n_in,
                              void* d_out, int out_size)
{
    const float* preds = (const float*)d_in[0];
    const int*   tgt   = (const int*)d_in[1];
    // d_in[2] = grid_size (always 8 for this problem's shapes)

    static int smem_set = 0;
    if (!smem_set) {
        cudaFuncSetAttribute(fused_kernel,
                             cudaFuncAttributeMaxDynamicSharedMemorySize,
                             NSTAGE * STAGE_BYTES);
        smem_set = 1;
    }
    fused_kernel<<<GRID, NTHREADS, NSTAGE * STAGE_BYTES>>>(tgt, preds, (float*)d_out);
}

// round 15
// speedup vs baseline: 1.0568x; 1.0568x over previous
#include <cuda_runtime.h>
#include <cstdint>

// Problem constants (fixed by dataset: B=16, H=1024, W=2048, G=8, C=19)
#define NB      524288
#define NC      19
#define WID     2048
#define HEI     1024
#define GS      8
#define BLOCKS_PER_TILE 128                    // half a block-row
#define NTILES  (NB/BLOCKS_PER_TILE)           // 4096
#define TGT_ROW_BYTES 4096                     // 1024 px * 4B per strip row
#define TGT_ROW_STRIDE 4112                    // +16B pad: bank-conflict-free masks
#define TGT_SPAN (8*TGT_ROW_STRIDE)            // 32896
#define PRED_BYTES (BLOCKS_PER_TILE*NC*4)      // 9728 (16B multiple)
#define STAGE_TX   (8*TGT_ROW_BYTES + PRED_BYTES)  // 42496 bytes transferred
#define STAGE_SPAN (TGT_SPAN + PRED_BYTES)         // 42624 smem layout span
#define NSTAGE  2
#define NTHREADS 512
#define GRID    304                            // 2 CTAs per SM
#define V_PER_TILE (BLOCKS_PER_TILE*NC/4)      // 608 float4

// Allocation-free scratch (__device__ globals per harness rules)
__device__ double       g_partials[GRID];
__device__ unsigned int g_count = 0;           // self-resetting completion counter

// Numerically stable softplus: max(x,0) + log(1 + exp(-|x|))
__device__ __forceinline__ float softplus_f(float x)
{
    float e = __expf(-fabsf(x));
    return fmaxf(x, 0.0f) + __logf(1.0f + e);
}

__device__ __forceinline__ void mbar_init(uint32_t mbar, unsigned count)
{
    asm volatile("mbarrier.init.shared.b64 [%0], %1;" :: "r"(mbar), "r"(count) : "memory");
}

__device__ __forceinline__ void mbar_wait(uint32_t mbar, unsigned phase)
{
    asm volatile(
        "{\n\t.reg .pred P;\n\t"
        "WAIT_%=:\n\t"
        "mbarrier.try_wait.parity.acquire.cta.shared::cta.b64 P, [%0], %1, 0x989680;\n\t"
        "@P bra DONE_%=;\n\t"
        "bra WAIT_%=;\n\t"
        "DONE_%=:\n\t}"
        :: "r"(mbar), "r"(phase) : "memory");
}

__device__ __forceinline__ void bulk_cp(uint32_t dst_smem, const void* src,
                                        unsigned bytes, uint32_t mbar)
{
    asm volatile(
        "cp.async.bulk.shared::cluster.global.mbarrier::complete_tx::bytes "
        "[%0], [%1], %2, [%3];"
        :: "r"(dst_smem), "l"(src), "r"(bytes), "r"(mbar) : "memory");
}

__device__ __forceinline__ const char* tile_tgt_src(const int* tgt, unsigned tile)
{
    unsigned half = tile & 1u;
    unsigned bh   = (tile >> 1) & 127u;
    unsigned bimg = tile >> 8;
    return (const char*)(tgt
        + ((size_t)(bimg * HEI + bh * GS)) * WID + (size_t)half * 1024u);
}

__device__ __forceinline__ void issue_targets(const int* tgt, unsigned tile,
                                              uint32_t stage, uint32_t mbar)
{
    asm volatile("mbarrier.arrive.expect_tx.shared.b64 _, [%0], %1;"
                 :: "r"(mbar), "r"((unsigned)STAGE_TX) : "memory");
    const char* tsrc = tile_tgt_src(tgt, tile);
#pragma unroll
    for (int r = 0; r < 8; r++)
        bulk_cp(stage + r * TGT_ROW_STRIDE, tsrc + (size_t)r * WID * 4,
                TGT_ROW_BYTES, mbar);
}

// ---------------------------------------------------------------------------
// 2-stage TMA pipeline, 512 threads, 2 CTAs/SM (85KB smem each).
// Doubled consumer: compute window per tile ~halves vs R12, so the TMA feed
// is the sole limiter. Split refill keeps requests flowing during compute.
// ---------------------------------------------------------------------------
__global__ void __launch_bounds__(NTHREADS)
fused_kernel(const int*   __restrict__ tgt,
             const float* __restrict__ preds,
             float*       __restrict__ out)
{
    extern __shared__ char stage_mem[];                 // NSTAGE * STAGE_SPAN
    __shared__ unsigned long long mbar_store[NSTAGE];
    __shared__ unsigned int sm_mask[BLOCKS_PER_TILE + 1];
    __shared__ float  ws[16];
    __shared__ double sh2[NTHREADS];

    const unsigned tid  = threadIdx.x;
    const unsigned lane = tid & 31u;
    const unsigned wix  = tid >> 5;                     // 0..15
    const unsigned cta  = blockIdx.x;

    const uint32_t stage0 = (uint32_t)__cvta_generic_to_shared(stage_mem);
    const uint32_t mbb    = (uint32_t)__cvta_generic_to_shared(&mbar_store[0]);

    if (tid == 0) {
        mbar_init(mbb, 1);
        mbar_init(mbb + 8u, 1);
        asm volatile("fence.proxy.async.shared::cta;" ::: "memory");
        // Prologue: fill both stages (every CTA has >= 13 tiles)
#pragma unroll
        for (unsigned k = 0; k < NSTAGE; k++) {
            uint32_t stg = stage0 + k * STAGE_SPAN;
            uint32_t mb  = mbb + 8u * k;
            issue_targets(tgt, cta + k * GRID, stg, mb);
            bulk_cp(stg + TGT_SPAN,
                    (const char*)preds + (size_t)(cta + k * GRID) * PRED_BYTES,
                    PRED_BYTES, mb);
        }
    }
    __syncthreads();

    float s = 0.0f;
    unsigned n = 0, ph0 = 0, ph1 = 0;

    for (unsigned tile = cta; tile < NTILES; tile += GRID, n++) {
        const unsigned k = n & 1u;
        const uint32_t  stg  = stage0 + k * STAGE_SPAN;
        const char*     stgp = stage_mem + (size_t)k * STAGE_SPAN;
        const uint32_t  mb   = mbb + 8u * k;
        const unsigned  nt   = tile + NSTAGE * GRID;    // refill tile (if any)

        if (k) { mbar_wait(mb, ph1); ph1 ^= 1u; }
        else   { mbar_wait(mb, ph0); ph0 ^= 1u; }

        // ---- masks: 4 threads per block (half h, row-group rg) ----
        // Row stride 4112B decorrelates rg=0/rg=1 banks: conflict-free LDS.128.
        {
            unsigned blk = tid >> 2;            // 0..127
            unsigned h   = tid & 1u;            // 16B half of the 32B block row
            unsigned rg  = (tid >> 1) & 1u;     // rows rg*4 .. rg*4+3
            unsigned m = 0u;
#pragma unroll
            for (int r = 0; r < 4; r++) {
                int4 v = *(const int4*)(stgp + (rg * 4u + r) * TGT_ROW_STRIDE
                                        + blk * 32u + h * 16u);
                m |= (1u << v.x) | (1u << v.y) | (1u << v.z) | (1u << v.w);
            }
            m |= __shfl_xor_sync(0xffffffffu, m, 1);   // merge halves
            m |= __shfl_xor_sync(0xffffffffu, m, 2);   // merge row groups
            if ((tid & 3u) == 0u) sm_mask[blk] = m;
            if (tid == 0u) sm_mask[BLOCKS_PER_TILE] = 0u;
        }
        __syncthreads();          // masks visible; targets region dead

        // refill targets early: overlaps the preds compute below
        if (tid == 0u && nt < NTILES)
            issue_targets(tgt, nt, stg, mb);

        // ---- preds: 608 float4 from smem, softplus + correction ----
        const float4* pvs = (const float4*)(stgp + TGT_SPAN);
#pragma unroll
        for (int it = 0; it < 2; it++) {
            unsigned j = tid + (unsigned)it * NTHREADS;
            if (it == 1 && tid >= (V_PER_TILE - NTHREADS)) break;  // tail: tid<96
            unsigned e0 = j * 4u;
            unsigned q  = e0 / 19u;                 // 0..127 (magic div)
            unsigned c0 = e0 - q * 19u;             // 0..18
            unsigned mm = (sm_mask[q] | (sm_mask[q + 1] << 19)) >> c0;
            float4 x = pvs[j];
            s += softplus_f(x.x) + softplus_f(x.y)
               + softplus_f(x.z) + softplus_f(x.w);
            if (mm & 1u) s -= x.x;
            if (mm & 2u) s -= x.y;
            if (mm & 4u) s -= x.z;
            if (mm & 8u) s -= x.w;
        }
        __syncthreads();          // all preds reads of this stage done

        // refill preds (completes the stage's expect_tx)
        if (tid == 0u && nt < NTILES)
            bulk_cp(stg + TGT_SPAN,
                    (const char*)preds + (size_t)nt * PRED_BYTES,
                    PRED_BYTES, mb);
    }

    // ---- per-CTA fixed-tree reduction -> double partial ----
#pragma unroll
    for (int o = 16; o > 0; o >>= 1)
        s += __shfl_xor_sync(0xffffffffu, s, o);
    if (lane == 0u) ws[wix] = s;
    __syncthreads();
    if (tid < 32u) {
        float v = (tid < 16u) ? ws[tid] : 0.0f;
#pragma unroll
        for (int o = 8; o > 0; o >>= 1)
            v += __shfl_xor_sync(0xffffffffu, v, o);
        if (tid == 0u) {
            g_partials[cta] = (double)v;
            __threadfence();
            unsigned done = atomicAdd(&g_count, 1u);
            ws[0] = (done == (unsigned)(GRID - 1)) ? 1.0f : 0.0f;
        }
    }
    __syncthreads();
    if (ws[0] == 0.0f) return;

    // ---- Last CTA: deterministic final reduction over CTA partials ----
    sh2[tid] = (tid < (unsigned)GRID) ? g_partials[tid] : 0.0;
    __syncthreads();
#pragma unroll
    for (int o = NTHREADS / 2; o > 0; o >>= 1) {
        if (tid < (unsigned)o) sh2[tid] += sh2[tid + o];
        __syncthreads();
    }
    if (tid == 0) {
        out[0] = (float)(sh2[0] / ((double)NB * (double)NC));
        g_count = 0;                     // reset for next graph replay
    }
}

// ---------------------------------------------------------------------------
extern "C" void kernel_launch(void* const* d_in, const int* in_sizes, int n_in,
                              void* d_out, int out_size)
{
    const float* preds = (const float*)d_in[0];
    const int*   tgt   = (const int*)d_in[1];
    // d_in[2] = grid_size (always 8 for this problem's shapes)

    static int smem_set = 0;
    if (!smem_set) {
        cudaFuncSetAttribute(fused_kernel,
                             cudaFuncAttributeMaxDynamicSharedMemorySize,
                             NSTAGE * STAGE_SPAN);
        smem_set = 1;
    }
    fused_kernel<<<GRID, NTHREADS, NSTAGE * STAGE_SPAN>>>(tgt, preds, (float*)d_out);
}